// round 4
// baseline (speedup 1.0000x reference)
#include <cuda_runtime.h>
#include <cuda_bf16.h>
#include <cstdint>
#include <cstddef>

// Problem constants
#define RR 8
#define NN 50000
#define EE 100000

// ---------------------------------------------------------------------------
// Scratch (device globals; no allocation allowed in kernel_launch)
// ---------------------------------------------------------------------------
__device__ float g_y[(size_t)RR * NN * 256];  // per-relation transformed feats
__device__ float g_agg[(size_t)NN * 256];     // summed relation means
__device__ float g_h[(size_t)NN * 256];       // layer-0 output
__device__ float g_cnt[RR * NN];              // edge counts -> inverse counts

// ---------------------------------------------------------------------------
// Count edges per (relation, target), then invert: inv = 1 / max(cnt, 1)
// ---------------------------------------------------------------------------
__global__ void count_kernel(const int* __restrict__ tgt, float* __restrict__ cnt)
{
    int i = blockIdx.x * blockDim.x + threadIdx.x;
    if (i >= RR * EE) return;
    int r = i / EE;
    atomicAdd(&cnt[r * NN + tgt[i]], 1.0f);
}

__global__ void invert_kernel(float* __restrict__ cnt)
{
    int i = blockIdx.x * blockDim.x + threadIdx.x;
    if (i >= RR * NN) return;
    cnt[i] = 1.0f / fmaxf(cnt[i], 1.0f);
}

// ---------------------------------------------------------------------------
// Scatter (256-wide): agg[tgt] += Y[r][src] * invcnt[r][tgt]
// One warp per edge; vector fp32 reductions (red.global.add.v4.f32).
// ---------------------------------------------------------------------------
__global__ void scatter256_kernel(const float* __restrict__ Y,
                                  const int* __restrict__ src,
                                  const int* __restrict__ tgt,
                                  const float* __restrict__ invcnt,
                                  float* __restrict__ agg)
{
    int gw = (blockIdx.x * blockDim.x + threadIdx.x) >> 5;
    if (gw >= RR * EE) return;
    int lane = threadIdx.x & 31;
    int r = gw / EE;
    int s = __ldg(&src[gw]);
    int t = __ldg(&tgt[gw]);
    float w = __ldg(&invcnt[r * NN + t]);

    const float4* yr = (const float4*)(Y + ((size_t)r * NN + s) * 256);
    float* ar = agg + (size_t)t * 256;

#pragma unroll
    for (int it = 0; it < 2; ++it) {
        int c = it * 32 + lane;
        float4 v = __ldg(&yr[c]);
        float* p = ar + (size_t)c * 4;
        asm volatile("red.global.add.v4.f32 [%0], {%1, %2, %3, %4};"
                     :: "l"(p), "f"(v.x * w), "f"(v.y * w), "f"(v.z * w), "f"(v.w * w)
                     : "memory");
    }
}

// ---------------------------------------------------------------------------
// SGEMM, BM=64 x BN=256 x BK=16, 256 threads, 8x8 microtile,
// double-buffered smem (register prefetch of the next K-tile).
//   SCALE: A row scaled by nw[row] during load (for the relation transform).
//   EPI:   epilogue out = LN(relu(acc + bias + agg[row])) (self+merge GEMM);
//          otherwise plain store.
// For the relation transform, gridDim.y = relation; B/C offset per relation.
// Warp ty owns rows [ty*8, ty*8+8) across all 256 cols -> LN via warp shuffles.
// ---------------------------------------------------------------------------
#define BM 64
#define BN 256
#define BK 16

template <int KSEG, bool SCALE, bool EPI>
__global__ __launch_bounds__(256, 2)
void gemm_kernel(const float* __restrict__ A,     // [M, KSEG]
                 const float* __restrict__ B,     // [gridDim.y, KSEG, 256]
                 const float* __restrict__ nw,    // [M] (SCALE only)
                 const float* __restrict__ agg,   // [M, 256] (EPI only)
                 const float* __restrict__ bias,  // [256]     (EPI only)
                 const float* __restrict__ ln_g,  // [256]     (EPI only)
                 const float* __restrict__ ln_b,  // [256]     (EPI only)
                 float* __restrict__ C,           // [gridDim.y, M, 256]
                 int M)
{
    __shared__ float As[2][BK][BM + 4];
    __shared__ float Bs[2][BK][BN];

    const int tid = threadIdx.x;
    const int tx = tid & 31;  // 32 column groups (cols tx*4 and 128+tx*4)
    const int ty = tid >> 5;  // 8 row groups (== warp id)
    const int row0 = blockIdx.x * BM;

    const float* Bp = B + (size_t)blockIdx.y * KSEG * 256;
    float* Cp = C + (size_t)blockIdx.y * M * 256;

    float acc[8][8];
#pragma unroll
    for (int i = 0; i < 8; ++i)
#pragma unroll
        for (int j = 0; j < 8; ++j) acc[i][j] = 0.0f;

    // A-tile load indices: each thread loads one float4 (64 rows x 16 k)
    const int ar = tid >> 2;        // 0..63
    const int ak = (tid & 3) * 4;   // 0,4,8,12
    const int arow = min(row0 + ar, M - 1);
    const float ascale = SCALE ? __ldg(&nw[arow]) : 1.0f;
    const float* Arow = A + (size_t)arow * KSEG;
    // B-tile load indices: each thread loads 4 float4s
    const int bcol = (tid & 63) * 4;   // 0..252
    const int bk0 = (tid >> 6) * 4;    // 0,4,8,12

    // Prefetch tile 0 into registers
    float4 pa = *(const float4*)(Arow + ak);
    float4 pb[4];
#pragma unroll
    for (int i = 0; i < 4; ++i)
        pb[i] = *(const float4*)(Bp + (size_t)(bk0 + i) * 256 + bcol);

    const int NKT = KSEG / BK;
    int buf = 0;

    for (int kt = 0; kt < NKT; ++kt) {
        // Commit prefetched registers to smem[buf]
        As[buf][ak + 0][ar] = pa.x * ascale;
        As[buf][ak + 1][ar] = pa.y * ascale;
        As[buf][ak + 2][ar] = pa.z * ascale;
        As[buf][ak + 3][ar] = pa.w * ascale;
#pragma unroll
        for (int i = 0; i < 4; ++i)
            *(float4*)&Bs[buf][bk0 + i][bcol] = pb[i];
        __syncthreads();

        // Prefetch next tile into registers (overlaps with compute below)
        if (kt + 1 < NKT) {
            int kn = (kt + 1) * BK;
            pa = *(const float4*)(Arow + kn + ak);
#pragma unroll
            for (int i = 0; i < 4; ++i)
                pb[i] = *(const float4*)(Bp + (size_t)(kn + bk0 + i) * 256 + bcol);
        }

#pragma unroll
        for (int k = 0; k < BK; ++k) {
            float4 a0 = *(const float4*)&As[buf][k][ty * 8];
            float4 a1 = *(const float4*)&As[buf][k][ty * 8 + 4];
            float4 b0 = *(const float4*)&Bs[buf][k][tx * 4];
            float4 b1 = *(const float4*)&Bs[buf][k][128 + tx * 4];
            float a[8] = {a0.x, a0.y, a0.z, a0.w, a1.x, a1.y, a1.z, a1.w};
            float b[8] = {b0.x, b0.y, b0.z, b0.w, b1.x, b1.y, b1.z, b1.w};
#pragma unroll
            for (int i = 0; i < 8; ++i)
#pragma unroll
                for (int j = 0; j < 8; ++j) acc[i][j] += a[i] * b[j];
        }
        buf ^= 1;
    }

    if (!EPI) {
        // Plain store
#pragma unroll
        for (int i = 0; i < 8; ++i) {
            int row = row0 + ty * 8 + i;
            if (row < M) {
                float4 o0 = {acc[i][0], acc[i][1], acc[i][2], acc[i][3]};
                float4 o1 = {acc[i][4], acc[i][5], acc[i][6], acc[i][7]};
                *(float4*)(Cp + (size_t)row * 256 + tx * 4) = o0;
                *(float4*)(Cp + (size_t)row * 256 + 128 + tx * 4) = o1;
            }
        }
        return;
    }

    // Epilogue: + bias + agg, relu, LayerNorm per row (warp owns full row).
    float4 bi0 = *(const float4*)(bias + tx * 4);
    float4 bi1 = *(const float4*)(bias + 128 + tx * 4);
    float4 g0 = *(const float4*)(ln_g + tx * 4);
    float4 g1 = *(const float4*)(ln_g + 128 + tx * 4);
    float4 be0 = *(const float4*)(ln_b + tx * 4);
    float4 be1 = *(const float4*)(ln_b + 128 + tx * 4);

#pragma unroll
    for (int i = 0; i < 8; ++i) {
        int row = row0 + ty * 8 + i;
        int crow = min(row, M - 1);
        float4 ag0 = __ldg((const float4*)(agg + (size_t)crow * 256 + tx * 4));
        float4 ag1 = __ldg((const float4*)(agg + (size_t)crow * 256 + 128 + tx * 4));
        float v[8];
        v[0] = acc[i][0] + bi0.x + ag0.x; v[1] = acc[i][1] + bi0.y + ag0.y;
        v[2] = acc[i][2] + bi0.z + ag0.z; v[3] = acc[i][3] + bi0.w + ag0.w;
        v[4] = acc[i][4] + bi1.x + ag1.x; v[5] = acc[i][5] + bi1.y + ag1.y;
        v[6] = acc[i][6] + bi1.z + ag1.z; v[7] = acc[i][7] + bi1.w + ag1.w;
#pragma unroll
        for (int j = 0; j < 8; ++j) v[j] = fmaxf(v[j], 0.0f);

        float s = 0.0f;
#pragma unroll
        for (int j = 0; j < 8; ++j) s += v[j];
#pragma unroll
        for (int o = 16; o > 0; o >>= 1) s += __shfl_xor_sync(0xffffffffu, s, o);
        float mu = s * (1.0f / 256.0f);

        float q = 0.0f;
#pragma unroll
        for (int j = 0; j < 8; ++j) { float d = v[j] - mu; q += d * d; }
#pragma unroll
        for (int o = 16; o > 0; o >>= 1) q += __shfl_xor_sync(0xffffffffu, q, o);
        float rs = rsqrtf(q * (1.0f / 256.0f) + 1e-5f);

        if (row < M) {
            float4 o0, o1;
            o0.x = (v[0] - mu) * rs * g0.x + be0.x;
            o0.y = (v[1] - mu) * rs * g0.y + be0.y;
            o0.z = (v[2] - mu) * rs * g0.z + be0.z;
            o0.w = (v[3] - mu) * rs * g0.w + be0.w;
            o1.x = (v[4] - mu) * rs * g1.x + be1.x;
            o1.y = (v[5] - mu) * rs * g1.y + be1.y;
            o1.z = (v[6] - mu) * rs * g1.z + be1.z;
            o1.w = (v[7] - mu) * rs * g1.w + be1.w;
            *(float4*)(Cp + (size_t)row * 256 + tx * 4) = o0;
            *(float4*)(Cp + (size_t)row * 256 + 128 + tx * 4) = o1;
        }
    }
}

// ---------------------------------------------------------------------------
// Host launcher
// ---------------------------------------------------------------------------
extern "C" void kernel_launch(void* const* d_in, const int* in_sizes, int n_in,
                              void* d_out, int out_size)
{
    const float* x       = (const float*)d_in[0];
    const float* nw      = (const float*)d_in[1];
    const int*   esrc    = (const int*)d_in[2];
    const int*   etgt    = (const int*)d_in[3];
    const float* Wrel0   = (const float*)d_in[4];
    const float* Wself0w = (const float*)d_in[5];
    const float* Wself0b = (const float*)d_in[6];
    const float* ln0g    = (const float*)d_in[7];
    const float* ln0b    = (const float*)d_in[8];
    const float* Wrel1   = (const float*)d_in[9];
    const float* Wself1w = (const float*)d_in[10];
    const float* Wself1b = (const float*)d_in[11];
    const float* ln1g    = (const float*)d_in[12];
    const float* ln1b    = (const float*)d_in[13];
    float* out = (float*)d_out;

    float *y, *agg, *h, *cnt;
    cudaGetSymbolAddress((void**)&y,   g_y);
    cudaGetSymbolAddress((void**)&agg, g_agg);
    cudaGetSymbolAddress((void**)&h,   g_h);
    cudaGetSymbolAddress((void**)&cnt, g_cnt);

    const int gx = (NN + BM - 1) / BM;        // 782
    const int scat_blocks = (RR * EE * 32 + 255) / 256;

    // Per-(relation,target) inverse neighbor counts (recomputed every call).
    cudaMemsetAsync(cnt, 0, (size_t)RR * NN * sizeof(float));
    count_kernel<<<(RR * EE + 255) / 256, 256>>>(etgt, cnt);
    invert_kernel<<<(RR * NN + 255) / 256, 256>>>(cnt);

    // ---- Layer 0 ----
    gemm_kernel<768, true, false><<<dim3(gx, RR), 256>>>(
        x, Wrel0, nw, nullptr, nullptr, nullptr, nullptr, y, NN);
    cudaMemsetAsync(agg, 0, (size_t)NN * 256 * sizeof(float));
    scatter256_kernel<<<scat_blocks, 256>>>(y, esrc, etgt, cnt, agg);
    gemm_kernel<768, false, true><<<dim3(gx, 1), 256>>>(
        x, Wself0w, nullptr, agg, Wself0b, ln0g, ln0b, h, NN);

    // ---- Layer 1 ----
    gemm_kernel<256, true, false><<<dim3(gx, RR), 256>>>(
        h, Wrel1, nw, nullptr, nullptr, nullptr, nullptr, y, NN);
    cudaMemsetAsync(agg, 0, (size_t)NN * 256 * sizeof(float));
    scatter256_kernel<<<scat_blocks, 256>>>(y, esrc, etgt, cnt, agg);
    gemm_kernel<256, false, true><<<dim3(gx, 1), 256>>>(
        h, Wself1w, nullptr, agg, Wself1b, ln1g, ln1b, out, NN);
}

// round 11
// speedup vs baseline: 1.7835x; 1.7835x over previous
#include <cuda_runtime.h>
#include <cuda_bf16.h>
#include <cstdint>
#include <cstddef>

// Problem constants
#define RR 8
#define NN 50000
#define EE 100000
#define NT 2304           // 9 * 256 output columns (block 0 = self, 1..8 = relations)

// ---------------------------------------------------------------------------
// Scratch (device globals)
// ---------------------------------------------------------------------------
__device__ __nv_bfloat16 g_a[(size_t)NN * 2304];   // A' = [Ah | Al | Ah], K' = 3K
__device__ __nv_bfloat16 g_bt[(size_t)NT * 2304];  // B' = [Bh | Bh | Bl] per row, K-major
__device__ float g_self[(size_t)NN * 256];
__device__ float g_y[(size_t)RR * NN * 256];
__device__ float g_agg[(size_t)NN * 256];
__device__ float g_h[(size_t)NN * 256];
__device__ float g_cnt[RR * NN];

// ---------------------------------------------------------------------------
// mma.sync / ldmatrix helpers (base-PTX compatible: sm_80+ instructions)
// ---------------------------------------------------------------------------
__device__ __forceinline__ uint32_t smem_u32(const void* p) {
    uint32_t a;
    asm("{ .reg .u64 t; cvta.to.shared.u64 t, %1; cvt.u32.u64 %0, t; }" : "=r"(a) : "l"(p));
    return a;
}

#define LDSM_X4(r0, r1, r2, r3, addr) \
    asm volatile("ldmatrix.sync.aligned.m8n8.x4.shared.b16 {%0,%1,%2,%3}, [%4];" \
                 : "=r"(r0), "=r"(r1), "=r"(r2), "=r"(r3) : "r"(addr))

#define MMA16816(d, a, b0, b1) \
    asm volatile("mma.sync.aligned.m16n8k16.row.col.f32.bf16.bf16.f32 " \
                 "{%0,%1,%2,%3}, {%4,%5,%6,%7}, {%8,%9}, {%0,%1,%2,%3};" \
                 : "+f"((d)[0]), "+f"((d)[1]), "+f"((d)[2]), "+f"((d)[3]) \
                 : "r"((a)[0]), "r"((a)[1]), "r"((a)[2]), "r"((a)[3]), "r"(b0), "r"(b1))

// ---------------------------------------------------------------------------
// Counts
// ---------------------------------------------------------------------------
__global__ void count_kernel(const int* __restrict__ tgt, float* __restrict__ cnt)
{
    int i = blockIdx.x * blockDim.x + threadIdx.x;
    if (i >= RR * EE) return;
    atomicAdd(&cnt[(i / EE) * NN + tgt[i]], 1.0f);
}
__global__ void invert_kernel(float* __restrict__ cnt)
{
    int i = blockIdx.x * blockDim.x + threadIdx.x;
    if (i >= RR * NN) return;
    cnt[i] = 1.0f / fmaxf(cnt[i], 1.0f);
}

// ---------------------------------------------------------------------------
// fp32 -> bf16 3-segment split: out[row][0:K]=hi, [K:2K]=lo, [2K:3K]=hi
// ---------------------------------------------------------------------------
template <int K>
__global__ void convert_split3_kernel(const float* __restrict__ in,
                                      __nv_bfloat16* __restrict__ out, int Nrows)
{
    size_t i = (size_t)blockIdx.x * blockDim.x + threadIdx.x;
    if (i >= (size_t)Nrows * (K / 4)) return;
    int row = (int)(i / (K / 4));
    int pos = (int)(i % (K / 4)) * 4;
    float4 v = ((const float4*)in)[i];
    __nv_bfloat16 h0 = __float2bfloat16(v.x), h1 = __float2bfloat16(v.y);
    __nv_bfloat16 h2 = __float2bfloat16(v.z), h3 = __float2bfloat16(v.w);
    __nv_bfloat162 H0(h0, h1), H1(h2, h3);
    __nv_bfloat162 L0(__float2bfloat16(v.x - __bfloat162float(h0)),
                      __float2bfloat16(v.y - __bfloat162float(h1)));
    __nv_bfloat162 L1(__float2bfloat16(v.z - __bfloat162float(h2)),
                      __float2bfloat16(v.w - __bfloat162float(h3)));
    __nv_bfloat16* base = out + (size_t)row * (3 * K) + pos;
    ((__nv_bfloat162*)(base))[0]         = H0;
    ((__nv_bfloat162*)(base))[1]         = H1;
    ((__nv_bfloat162*)(base + K))[0]     = L0;
    ((__nv_bfloat162*)(base + K))[1]     = L1;
    ((__nv_bfloat162*)(base + 2 * K))[0] = H0;
    ((__nv_bfloat162*)(base + 2 * K))[1] = H1;
}

// ---------------------------------------------------------------------------
// Weight transpose + 3-segment split: Bt[j*256+n][0:K]=hi, [K:2K]=hi, [2K:3K]=lo
// (pairs with A segments [Ah, Al, Ah] -> AhBh + AlBh + AhBl)
// ---------------------------------------------------------------------------
template <int K>
__global__ void wtrans3_kernel(const float* __restrict__ Wself,
                               const float* __restrict__ Wrel,
                               __nv_bfloat16* __restrict__ Bt)
{
    __shared__ float t[32][33];
    int k0 = blockIdx.x * 32, n0g = blockIdx.y * 32;
    int j = n0g / 256, ncol0 = n0g % 256;
    const float* W = (j == 0) ? Wself : (Wrel + (size_t)(j - 1) * K * 256);
    int tx = threadIdx.x & 31, ty = threadIdx.x >> 5;
    for (int yy = ty; yy < 32; yy += 8)
        t[yy][tx] = W[(size_t)(k0 + yy) * 256 + ncol0 + tx];
    __syncthreads();
    for (int yy = ty; yy < 32; yy += 8) {
        float v = t[tx][yy];
        __nv_bfloat16 h = __float2bfloat16(v);
        __nv_bfloat16 l = __float2bfloat16(v - __bfloat162float(h));
        size_t o = (size_t)(n0g + yy) * (3 * K) + k0 + tx;
        Bt[o]         = h;
        Bt[o + K]     = h;
        Bt[o + 2 * K] = l;
    }
}

// ---------------------------------------------------------------------------
// HMMA bf16 GEMM via mma.sync.m16n8k16. CTA tile 128x128, BK=32, 8 warps (4x2),
// warp tile 32x64. Smem rows padded to 40 halves (80B stride: conflict-free
// ldmatrix). Register-prefetch double buffering. Grid: (NT/128=18, ceil(M/128))
// with x = n-block so consecutive CTAs reuse the A tile in L2.
// Output: global col < 256 -> Cself; else relation (col>>8)-1 of Yrel.
// ---------------------------------------------------------------------------
#define PADK 40

template <int KP>
__global__ __launch_bounds__(256, 2)
void hmma_gemm_kernel(const __nv_bfloat16* __restrict__ A,   // [M, KP]
                      const __nv_bfloat16* __restrict__ Bt,  // [NT, KP]
                      float* __restrict__ Cself,             // [M, 256]
                      float* __restrict__ Yrel,              // [8, M, 256]
                      int M)
{
    __shared__ __nv_bfloat16 As[2][128 * PADK];
    __shared__ __nv_bfloat16 Bs[2][128 * PADK];

    const int tid = threadIdx.x;
    const int lane = tid & 31, wid = tid >> 5;
    const int warp_m = wid & 3;   // 4 warps over M (32 rows each)
    const int warp_n = wid >> 2;  // 2 warps over N (64 cols each)
    const int row0 = blockIdx.y * 128;
    const int n0 = blockIdx.x * 128;

    // Global load indices: 512 16B-chunks per tile, 2 per thread.
    const int c0 = tid, c1 = tid + 256;
    const int ar0 = min(row0 + (c0 >> 2), M - 1), ak0 = (c0 & 3) * 8;
    const int ar1 = min(row0 + (c1 >> 2), M - 1), ak1 = (c1 & 3) * 8;
    const int br0 = n0 + (c0 >> 2);
    const int br1 = n0 + (c1 >> 2);

    float acc[2][8][4];
#pragma unroll
    for (int i = 0; i < 2; ++i)
#pragma unroll
        for (int j = 0; j < 8; ++j)
#pragma unroll
            for (int e = 0; e < 4; ++e) acc[i][j][e] = 0.0f;

    uint4 pa0 = *(const uint4*)(A + (size_t)ar0 * KP + ak0);
    uint4 pa1 = *(const uint4*)(A + (size_t)ar1 * KP + ak1);
    uint4 pb0 = *(const uint4*)(Bt + (size_t)br0 * KP + ak0);
    uint4 pb1 = *(const uint4*)(Bt + (size_t)br1 * KP + ak1);

    // ldmatrix lane-dependent address parts
    const int a_r = lane & 15, a_c = (lane >> 4) * 8;                 // A: rows m, 16B col sel
    const int b_r = ((lane & 16) >> 1) + (lane & 7), b_c = (lane & 8) ? 8 : 0;  // B: rows n

    const int NKT = KP / 32;
    int buf = 0;

    for (int kt = 0; kt < NKT; ++kt) {
        *(uint4*)&As[buf][(c0 >> 2) * PADK + ak0] = pa0;
        *(uint4*)&As[buf][(c1 >> 2) * PADK + ak1] = pa1;
        *(uint4*)&Bs[buf][(c0 >> 2) * PADK + ak0] = pb0;
        *(uint4*)&Bs[buf][(c1 >> 2) * PADK + ak1] = pb1;
        __syncthreads();

        if (kt + 1 < NKT) {
            int kk = (kt + 1) * 32;
            pa0 = *(const uint4*)(A + (size_t)ar0 * KP + kk + ak0);
            pa1 = *(const uint4*)(A + (size_t)ar1 * KP + kk + ak1);
            pb0 = *(const uint4*)(Bt + (size_t)br0 * KP + kk + ak0);
            pb1 = *(const uint4*)(Bt + (size_t)br1 * KP + kk + ak1);
        }

        const uint32_t abase = smem_u32(&As[buf][0]) + ((warp_m * 32 + a_r) * PADK + a_c) * 2;
        const uint32_t bbase = smem_u32(&Bs[buf][0]) + ((warp_n * 64 + b_r) * PADK + b_c) * 2;

#pragma unroll
        for (int k16 = 0; k16 < 2; ++k16) {
            uint32_t af[2][4], bfr[4][4];
#pragma unroll
            for (int mi = 0; mi < 2; ++mi)
                LDSM_X4(af[mi][0], af[mi][1], af[mi][2], af[mi][3],
                        abase + mi * 16 * PADK * 2 + k16 * 32);
#pragma unroll
            for (int bi = 0; bi < 4; ++bi)
                LDSM_X4(bfr[bi][0], bfr[bi][1], bfr[bi][2], bfr[bi][3],
                        bbase + bi * 16 * PADK * 2 + k16 * 32);
#pragma unroll
            for (int mi = 0; mi < 2; ++mi)
#pragma unroll
                for (int nj = 0; nj < 8; ++nj)
                    MMA16816(acc[mi][nj], af[mi],
                             bfr[nj >> 1][(nj & 1) * 2], bfr[nj >> 1][(nj & 1) * 2 + 1]);
        }
        buf ^= 1;
    }

    // Epilogue: c0,c1 -> (row lane/4, col (lane%4)*2); c2,c3 -> row+8.
    const int m_lane = lane >> 2;
    const int c_lane = (lane & 3) * 2;
#pragma unroll
    for (int mi = 0; mi < 2; ++mi) {
#pragma unroll
        for (int half = 0; half < 2; ++half) {
            int row = row0 + warp_m * 32 + mi * 16 + half * 8 + m_lane;
            if (row < M) {
#pragma unroll
                for (int nj = 0; nj < 8; ++nj) {
                    int gcol = n0 + warp_n * 64 + nj * 8 + c_lane;
                    float* dst;
                    if (gcol < 256)
                        dst = Cself + (size_t)row * 256 + gcol;
                    else
                        dst = Yrel + (size_t)((gcol >> 8) - 1) * M * 256
                                   + (size_t)row * 256 + (gcol & 255);
                    *(float2*)dst = make_float2(acc[mi][nj][half * 2],
                                                acc[mi][nj][half * 2 + 1]);
                }
            }
        }
    }
}

// ---------------------------------------------------------------------------
// agg = self + bias
// ---------------------------------------------------------------------------
__global__ void init_agg_kernel(const float* __restrict__ self,
                                const float* __restrict__ bias,
                                float* __restrict__ agg)
{
    size_t i = (size_t)blockIdx.x * blockDim.x + threadIdx.x;
    if (i >= (size_t)NN * 64) return;
    float4 s = ((const float4*)self)[i];
    float4 b = ((const float4*)bias)[i & 63];
    ((float4*)agg)[i] = make_float4(s.x + b.x, s.y + b.y, s.z + b.z, s.w + b.w);
}

// ---------------------------------------------------------------------------
// Scatter: agg[tgt] += Y[r][src] * nw[src] * invcnt[r][tgt]
// ---------------------------------------------------------------------------
__global__ void scatter256_kernel(const float* __restrict__ Y,
                                  const int* __restrict__ src,
                                  const int* __restrict__ tgt,
                                  const float* __restrict__ nw,
                                  const float* __restrict__ invcnt,
                                  float* __restrict__ agg)
{
    int gw = (blockIdx.x * blockDim.x + threadIdx.x) >> 5;
    if (gw >= RR * EE) return;
    int lane = threadIdx.x & 31;
    int r = gw / EE;
    int s = __ldg(&src[gw]);
    int t = __ldg(&tgt[gw]);
    float w = __ldg(&nw[s]) * __ldg(&invcnt[r * NN + t]);

    const float4* yr = (const float4*)(Y + ((size_t)r * NN + s) * 256);
    float* ar = agg + (size_t)t * 256;
#pragma unroll
    for (int it = 0; it < 2; ++it) {
        int c = it * 32 + lane;
        float4 v = __ldg(&yr[c]);
        float* p = ar + (size_t)c * 4;
        asm volatile("red.global.add.v4.f32 [%0], {%1, %2, %3, %4};"
                     :: "l"(p), "f"(v.x * w), "f"(v.y * w), "f"(v.z * w), "f"(v.w * w)
                     : "memory");
    }
}

// ---------------------------------------------------------------------------
// out = LayerNorm(relu(agg)); one warp per row
// ---------------------------------------------------------------------------
__global__ void ln_kernel(const float* __restrict__ agg,
                          const float* __restrict__ g,
                          const float* __restrict__ b,
                          float* __restrict__ out)
{
    int row = blockIdx.x * 8 + (threadIdx.x >> 5);
    if (row >= NN) return;
    int lane = threadIdx.x & 31;
    const float4* ar = (const float4*)(agg + (size_t)row * 256);
    float4 v0 = ar[lane], v1 = ar[32 + lane];
    v0.x = fmaxf(v0.x, 0.f); v0.y = fmaxf(v0.y, 0.f); v0.z = fmaxf(v0.z, 0.f); v0.w = fmaxf(v0.w, 0.f);
    v1.x = fmaxf(v1.x, 0.f); v1.y = fmaxf(v1.y, 0.f); v1.z = fmaxf(v1.z, 0.f); v1.w = fmaxf(v1.w, 0.f);

    float s = v0.x + v0.y + v0.z + v0.w + v1.x + v1.y + v1.z + v1.w;
#pragma unroll
    for (int o = 16; o > 0; o >>= 1) s += __shfl_xor_sync(0xffffffffu, s, o);
    float mu = s * (1.0f / 256.0f);
    float q = (v0.x - mu) * (v0.x - mu) + (v0.y - mu) * (v0.y - mu)
            + (v0.z - mu) * (v0.z - mu) + (v0.w - mu) * (v0.w - mu)
            + (v1.x - mu) * (v1.x - mu) + (v1.y - mu) * (v1.y - mu)
            + (v1.z - mu) * (v1.z - mu) + (v1.w - mu) * (v1.w - mu);
#pragma unroll
    for (int o = 16; o > 0; o >>= 1) q += __shfl_xor_sync(0xffffffffu, q, o);
    float rs = rsqrtf(q * (1.0f / 256.0f) + 1e-5f);

    const float4* gp = (const float4*)g;
    const float4* bp = (const float4*)b;
    float4 g0 = gp[lane], g1 = gp[32 + lane], b0 = bp[lane], b1 = bp[32 + lane];
    float4 o0, o1;
    o0.x = (v0.x - mu) * rs * g0.x + b0.x; o0.y = (v0.y - mu) * rs * g0.y + b0.y;
    o0.z = (v0.z - mu) * rs * g0.z + b0.z; o0.w = (v0.w - mu) * rs * g0.w + b0.w;
    o1.x = (v1.x - mu) * rs * g1.x + b1.x; o1.y = (v1.y - mu) * rs * g1.y + b1.y;
    o1.z = (v1.z - mu) * rs * g1.z + b1.z; o1.w = (v1.w - mu) * rs * g1.w + b1.w;
    float4* op = (float4*)(out + (size_t)row * 256);
    op[lane] = o0; op[32 + lane] = o1;
}

// ---------------------------------------------------------------------------
// Host launcher
// ---------------------------------------------------------------------------
extern "C" void kernel_launch(void* const* d_in, const int* in_sizes, int n_in,
                              void* d_out, int out_size)
{
    const float* x       = (const float*)d_in[0];
    const float* nw      = (const float*)d_in[1];
    const int*   esrc    = (const int*)d_in[2];
    const int*   etgt    = (const int*)d_in[3];
    const float* Wrel0   = (const float*)d_in[4];
    const float* Wself0w = (const float*)d_in[5];
    const float* Wself0b = (const float*)d_in[6];
    const float* ln0g    = (const float*)d_in[7];
    const float* ln0b    = (const float*)d_in[8];
    const float* Wrel1   = (const float*)d_in[9];
    const float* Wself1w = (const float*)d_in[10];
    const float* Wself1b = (const float*)d_in[11];
    const float* ln1g    = (const float*)d_in[12];
    const float* ln1b    = (const float*)d_in[13];
    float* out = (float*)d_out;

    __nv_bfloat16 *a, *bt;
    float *selfb, *y, *agg, *h, *cnt;
    cudaGetSymbolAddress((void**)&a,     g_a);
    cudaGetSymbolAddress((void**)&bt,    g_bt);
    cudaGetSymbolAddress((void**)&selfb, g_self);
    cudaGetSymbolAddress((void**)&y,     g_y);
    cudaGetSymbolAddress((void**)&agg,   g_agg);
    cudaGetSymbolAddress((void**)&h,     g_h);
    cudaGetSymbolAddress((void**)&cnt,   g_cnt);

    const int gy = (NN + 127) / 128;          // 391 m-blocks
    const int gnx = NT / 128;                 // 18 n-blocks
    const int scat_blocks = (RR * EE * 32 + 255) / 256;

    // Inverse neighbor counts
    cudaMemsetAsync(cnt, 0, (size_t)RR * NN * sizeof(float));
    count_kernel<<<(RR * EE + 255) / 256, 256>>>(etgt, cnt);
    invert_kernel<<<(RR * NN + 255) / 256, 256>>>(cnt);

    // ---- Layer 0 (K=768, K'=2304) ----
    convert_split3_kernel<768><<<(int)(((size_t)NN * 192 + 255) / 256), 256>>>(x, a, NN);
    wtrans3_kernel<768><<<dim3(768 / 32, NT / 32), 256>>>(Wself0w, Wrel0, bt);
    hmma_gemm_kernel<2304><<<dim3(gnx, gy), 256>>>(a, bt, selfb, y, NN);
    init_agg_kernel<<<(int)(((size_t)NN * 64 + 255) / 256), 256>>>(selfb, Wself0b, agg);
    scatter256_kernel<<<scat_blocks, 256>>>(y, esrc, etgt, nw, cnt, agg);
    ln_kernel<<<(NN + 7) / 8, 256>>>(agg, ln0g, ln0b, h);

    // ---- Layer 1 (K=256, K'=768) ----
    convert_split3_kernel<256><<<(int)(((size_t)NN * 64 + 255) / 256), 256>>>(h, a, NN);
    wtrans3_kernel<256><<<dim3(256 / 32, NT / 32), 256>>>(Wself1w, Wrel1, bt);
    hmma_gemm_kernel<768><<<dim3(gnx, gy), 256>>>(a, bt, selfb, y, NN);
    init_agg_kernel<<<(int)(((size_t)NN * 64 + 255) / 256), 256>>>(selfb, Wself1b, agg);
    scatter256_kernel<<<scat_blocks, 256>>>(y, esrc, etgt, nw, cnt, agg);
    ln_kernel<<<(NN + 7) / 8, 256>>>(agg, ln1g, ln1b, out);
}

// round 15
// speedup vs baseline: 2.0320x; 1.1393x over previous
#include <cuda_runtime.h>
#include <cuda_bf16.h>
#include <cstdint>
#include <cstddef>

// Problem constants
#define RR 8
#define NN 50000
#define EE 100000
#define NT 2304           // 9 * 256 output columns (block 0 = self, 1..8 = relations)

// ---------------------------------------------------------------------------
// Scratch (device globals)
// ---------------------------------------------------------------------------
__device__ __nv_bfloat16 g_a[(size_t)NN * 2304];   // A' = [Ah | Al | Ah], K' = 3K
__device__ __nv_bfloat16 g_bt[(size_t)NT * 2304];  // B' = [Bh | Bh | Bl] per row, K-major
__device__ float g_self[(size_t)NN * 256];
__device__ float g_y[(size_t)RR * NN * 256];
__device__ float g_agg[(size_t)NN * 256];
__device__ float g_cnt[RR * NN];

// ---------------------------------------------------------------------------
// mma.sync / ldmatrix / cp.async helpers (base-PTX, sm_80+)
// ---------------------------------------------------------------------------
__device__ __forceinline__ uint32_t smem_u32(const void* p) {
    uint32_t a;
    asm("{ .reg .u64 t; cvta.to.shared.u64 t, %1; cvt.u32.u64 %0, t; }" : "=r"(a) : "l"(p));
    return a;
}

#define LDSM_X4(r0, r1, r2, r3, addr) \
    asm volatile("ldmatrix.sync.aligned.m8n8.x4.shared.b16 {%0,%1,%2,%3}, [%4];" \
                 : "=r"(r0), "=r"(r1), "=r"(r2), "=r"(r3) : "r"(addr))

#define MMA16816(d, a, b0, b1) \
    asm volatile("mma.sync.aligned.m16n8k16.row.col.f32.bf16.bf16.f32 " \
                 "{%0,%1,%2,%3}, {%4,%5,%6,%7}, {%8,%9}, {%0,%1,%2,%3};" \
                 : "+f"((d)[0]), "+f"((d)[1]), "+f"((d)[2]), "+f"((d)[3]) \
                 : "r"((a)[0]), "r"((a)[1]), "r"((a)[2]), "r"((a)[3]), "r"(b0), "r"(b1))

#define CP16(dst, src) \
    asm volatile("cp.async.cg.shared.global [%0], [%1], 16;" :: "r"(dst), "l"(src))
#define CP_COMMIT() asm volatile("cp.async.commit_group;")
#define CP_WAIT1()  asm volatile("cp.async.wait_group 1;")

// ---------------------------------------------------------------------------
// Counts
// ---------------------------------------------------------------------------
__global__ void count_kernel(const int* __restrict__ tgt, float* __restrict__ cnt)
{
    int i = blockIdx.x * blockDim.x + threadIdx.x;
    if (i >= RR * EE) return;
    atomicAdd(&cnt[(i / EE) * NN + tgt[i]], 1.0f);
}
__global__ void invert_kernel(float* __restrict__ cnt)
{
    int i = blockIdx.x * blockDim.x + threadIdx.x;
    if (i >= RR * NN) return;
    cnt[i] = 1.0f / fmaxf(cnt[i], 1.0f);
}

// ---------------------------------------------------------------------------
// fp32 -> bf16 3-segment split: out[row][0:K]=hi, [K:2K]=lo, [2K:3K]=hi
// ---------------------------------------------------------------------------
template <int K>
__global__ void convert_split3_kernel(const float* __restrict__ in,
                                      __nv_bfloat16* __restrict__ out, int Nrows)
{
    size_t i = (size_t)blockIdx.x * blockDim.x + threadIdx.x;
    if (i >= (size_t)Nrows * (K / 4)) return;
    int row = (int)(i / (K / 4));
    int pos = (int)(i % (K / 4)) * 4;
    float4 v = ((const float4*)in)[i];
    __nv_bfloat16 h0 = __float2bfloat16(v.x), h1 = __float2bfloat16(v.y);
    __nv_bfloat16 h2 = __float2bfloat16(v.z), h3 = __float2bfloat16(v.w);
    __nv_bfloat162 H0(h0, h1), H1(h2, h3);
    __nv_bfloat162 L0(__float2bfloat16(v.x - __bfloat162float(h0)),
                      __float2bfloat16(v.y - __bfloat162float(h1)));
    __nv_bfloat162 L1(__float2bfloat16(v.z - __bfloat162float(h2)),
                      __float2bfloat16(v.w - __bfloat162float(h3)));
    __nv_bfloat16* base = out + (size_t)row * (3 * K) + pos;
    ((__nv_bfloat162*)(base))[0]         = H0;
    ((__nv_bfloat162*)(base))[1]         = H1;
    ((__nv_bfloat162*)(base + K))[0]     = L0;
    ((__nv_bfloat162*)(base + K))[1]     = L1;
    ((__nv_bfloat162*)(base + 2 * K))[0] = H0;
    ((__nv_bfloat162*)(base + 2 * K))[1] = H1;
}

// ---------------------------------------------------------------------------
// Weight transpose + 3-segment split: Bt[j*256+n][0:K]=hi, [K:2K]=hi, [2K:3K]=lo
// ---------------------------------------------------------------------------
template <int K>
__global__ void wtrans3_kernel(const float* __restrict__ Wself,
                               const float* __restrict__ Wrel,
                               __nv_bfloat16* __restrict__ Bt)
{
    __shared__ float t[32][33];
    int k0 = blockIdx.x * 32, n0g = blockIdx.y * 32;
    int j = n0g / 256, ncol0 = n0g % 256;
    const float* W = (j == 0) ? Wself : (Wrel + (size_t)(j - 1) * K * 256);
    int tx = threadIdx.x & 31, ty = threadIdx.x >> 5;
    for (int yy = ty; yy < 32; yy += 8)
        t[yy][tx] = W[(size_t)(k0 + yy) * 256 + ncol0 + tx];
    __syncthreads();
    for (int yy = ty; yy < 32; yy += 8) {
        float v = t[tx][yy];
        __nv_bfloat16 h = __float2bfloat16(v);
        __nv_bfloat16 l = __float2bfloat16(v - __bfloat162float(h));
        size_t o = (size_t)(n0g + yy) * (3 * K) + k0 + tx;
        Bt[o]         = h;
        Bt[o + K]     = h;
        Bt[o + 2 * K] = l;
    }
}

// ---------------------------------------------------------------------------
// HMMA bf16 GEMM via mma.sync.m16n8k16, cp.async 3-stage pipeline.
// CTA tile 128x128, BK=32, 8 warps (4x2), warp tile 32x64. Smem rows padded
// to 40 halves (conflict-free ldmatrix). Grid: (NT/128, ceil(M/128)),
// x = n-block so consecutive CTAs reuse the A tile in L2.
// ---------------------------------------------------------------------------
#define PADK 40
#define STAGE_ELEMS (128 * PADK)          // 5120 bf16 per array per stage
#define STAGE_BYTES (STAGE_ELEMS * 2)     // 10240
#define GEMM_SMEM   (6 * STAGE_BYTES)     // 3 stages x (A + B) = 61440

template <int KP>
__global__ __launch_bounds__(256, 2)
void hmma_gemm_kernel(const __nv_bfloat16* __restrict__ A,   // [M, KP]
                      const __nv_bfloat16* __restrict__ Bt,  // [NT, KP]
                      float* __restrict__ Cself,             // [M, 256]
                      float* __restrict__ Yrel,              // [8, M, 256]
                      int M)
{
    extern __shared__ __nv_bfloat16 sm[];
    __nv_bfloat16* As = sm;                       // [3][STAGE_ELEMS]
    __nv_bfloat16* Bs = sm + 3 * STAGE_ELEMS;     // [3][STAGE_ELEMS]

    const int tid = threadIdx.x;
    const int lane = tid & 31, wid = tid >> 5;
    const int warp_m = wid & 3;
    const int warp_n = wid >> 2;
    const int row0 = blockIdx.y * 128;
    const int n0 = blockIdx.x * 128;

    // Global->smem copy indices: 512 16B-chunks per tile per array, 2/thread.
    const int c0 = tid, c1 = tid + 256;
    const int ar0 = min(row0 + (c0 >> 2), M - 1), ak0 = (c0 & 3) * 8;
    const int ar1 = min(row0 + (c1 >> 2), M - 1), ak1 = (c1 & 3) * 8;
    const int br0 = n0 + (c0 >> 2);
    const int br1 = n0 + (c1 >> 2);

    const uint32_t as_base = smem_u32(As);
    const uint32_t bs_base = smem_u32(Bs);
    const uint32_t dA0 = as_base + ((c0 >> 2) * PADK + ak0) * 2;
    const uint32_t dA1 = as_base + ((c1 >> 2) * PADK + ak1) * 2;
    const uint32_t dB0 = bs_base + ((c0 >> 2) * PADK + ak0) * 2;
    const uint32_t dB1 = bs_base + ((c1 >> 2) * PADK + ak1) * 2;
    const char* sA0 = (const char*)(A + (size_t)ar0 * KP + ak0);
    const char* sA1 = (const char*)(A + (size_t)ar1 * KP + ak1);
    const char* sB0 = (const char*)(Bt + (size_t)br0 * KP + ak0);
    const char* sB1 = (const char*)(Bt + (size_t)br1 * KP + ak1);

    float acc[2][8][4];
#pragma unroll
    for (int i = 0; i < 2; ++i)
#pragma unroll
        for (int j = 0; j < 8; ++j)
#pragma unroll
            for (int e = 0; e < 4; ++e) acc[i][j][e] = 0.0f;

    // ldmatrix lane-dependent address parts (mapping validated in round 11)
    const int a_r = lane & 15, a_c = (lane >> 4) * 8;
    const int b_r = ((lane & 16) >> 1) + (lane & 7), b_c = (lane & 8) ? 8 : 0;

    const int NKT = KP / 32;

    // Prologue: issue stages 0 and 1
#pragma unroll
    for (int p = 0; p < 2; ++p) {
        uint32_t so = p * STAGE_BYTES;
        size_t go = (size_t)p * 64;  // 32 bf16 = 64 bytes per K-chunk
        CP16(dA0 + so, sA0 + go);
        CP16(dA1 + so, sA1 + go);
        CP16(dB0 + so, sB0 + go);
        CP16(dB1 + so, sB1 + go);
        CP_COMMIT();
    }

    for (int kt = 0; kt < NKT; ++kt) {
        CP_WAIT1();
        __syncthreads();

        const int s = kt % 3;
        const uint32_t abase = as_base + s * STAGE_BYTES
                             + ((warp_m * 32 + a_r) * PADK + a_c) * 2;
        const uint32_t bbase = bs_base + s * STAGE_BYTES
                             + ((warp_n * 64 + b_r) * PADK + b_c) * 2;

#pragma unroll
        for (int k16 = 0; k16 < 2; ++k16) {
            uint32_t af[2][4], bfr[4][4];
#pragma unroll
            for (int mi = 0; mi < 2; ++mi)
                LDSM_X4(af[mi][0], af[mi][1], af[mi][2], af[mi][3],
                        abase + mi * 16 * PADK * 2 + k16 * 32);
#pragma unroll
            for (int bi = 0; bi < 4; ++bi)
                LDSM_X4(bfr[bi][0], bfr[bi][1], bfr[bi][2], bfr[bi][3],
                        bbase + bi * 16 * PADK * 2 + k16 * 32);
#pragma unroll
            for (int mi = 0; mi < 2; ++mi)
#pragma unroll
                for (int nj = 0; nj < 8; ++nj)
                    MMA16816(acc[mi][nj], af[mi],
                             bfr[nj >> 1][(nj & 1) * 2], bfr[nj >> 1][(nj & 1) * 2 + 1]);
        }

        if (kt + 2 < NKT) {
            uint32_t so = ((kt + 2) % 3) * STAGE_BYTES;
            size_t go = (size_t)(kt + 2) * 64;
            CP16(dA0 + so, sA0 + go);
            CP16(dA1 + so, sA1 + go);
            CP16(dB0 + so, sB0 + go);
            CP16(dB1 + so, sB1 + go);
        }
        CP_COMMIT();
    }

    // Epilogue
    const int m_lane = lane >> 2;
    const int c_lane = (lane & 3) * 2;
#pragma unroll
    for (int mi = 0; mi < 2; ++mi) {
#pragma unroll
        for (int half = 0; half < 2; ++half) {
            int row = row0 + warp_m * 32 + mi * 16 + half * 8 + m_lane;
            if (row < M) {
#pragma unroll
                for (int nj = 0; nj < 8; ++nj) {
                    int gcol = n0 + warp_n * 64 + nj * 8 + c_lane;
                    float* dst;
                    if (gcol < 256)
                        dst = Cself + (size_t)row * 256 + gcol;
                    else
                        dst = Yrel + (size_t)((gcol >> 8) - 1) * M * 256
                                   + (size_t)row * 256 + (gcol & 255);
                    *(float2*)dst = make_float2(acc[mi][nj][half * 2],
                                                acc[mi][nj][half * 2 + 1]);
                }
            }
        }
    }
}

// ---------------------------------------------------------------------------
// agg = self + bias
// ---------------------------------------------------------------------------
__global__ void init_agg_kernel(const float* __restrict__ self,
                                const float* __restrict__ bias,
                                float* __restrict__ agg)
{
    size_t i = (size_t)blockIdx.x * blockDim.x + threadIdx.x;
    if (i >= (size_t)NN * 64) return;
    float4 s = ((const float4*)self)[i];
    float4 b = ((const float4*)bias)[i & 63];
    ((float4*)agg)[i] = make_float4(s.x + b.x, s.y + b.y, s.z + b.z, s.w + b.w);
}

// ---------------------------------------------------------------------------
// Scatter: agg[tgt] += Y[r][src] * nw[src] * invcnt[r][tgt]
// ---------------------------------------------------------------------------
__global__ void scatter256_kernel(const float* __restrict__ Y,
                                  const int* __restrict__ src,
                                  const int* __restrict__ tgt,
                                  const float* __restrict__ nw,
                                  const float* __restrict__ invcnt,
                                  float* __restrict__ agg)
{
    int gw = (blockIdx.x * blockDim.x + threadIdx.x) >> 5;
    if (gw >= RR * EE) return;
    int lane = threadIdx.x & 31;
    int r = gw / EE;
    int s = __ldg(&src[gw]);
    int t = __ldg(&tgt[gw]);
    float w = __ldg(&nw[s]) * __ldg(&invcnt[r * NN + t]);

    const float4* yr = (const float4*)(Y + ((size_t)r * NN + s) * 256);
    float* ar = agg + (size_t)t * 256;
#pragma unroll
    for (int it = 0; it < 2; ++it) {
        int c = it * 32 + lane;
        float4 v = __ldg(&yr[c]);
        float* p = ar + (size_t)c * 4;
        asm volatile("red.global.add.v4.f32 [%0], {%1, %2, %3, %4};"
                     :: "l"(p), "f"(v.x * w), "f"(v.y * w), "f"(v.z * w), "f"(v.w * w)
                     : "memory");
    }
}

// ---------------------------------------------------------------------------
// LayerNorm(relu(agg)); one warp per row. SPLIT: write bf16 [Ah|Al|Ah] rows
// (K=256 -> 768 cols) for the next layer's GEMM instead of float output.
// ---------------------------------------------------------------------------
template <bool SPLIT>
__global__ void ln_kernel(const float* __restrict__ agg,
                          const float* __restrict__ g,
                          const float* __restrict__ b,
                          float* __restrict__ out,           // !SPLIT
                          __nv_bfloat16* __restrict__ split) // SPLIT
{
    int row = blockIdx.x * 8 + (threadIdx.x >> 5);
    if (row >= NN) return;
    int lane = threadIdx.x & 31;
    const float4* ar = (const float4*)(agg + (size_t)row * 256);
    float4 v0 = ar[lane], v1 = ar[32 + lane];
    v0.x = fmaxf(v0.x, 0.f); v0.y = fmaxf(v0.y, 0.f); v0.z = fmaxf(v0.z, 0.f); v0.w = fmaxf(v0.w, 0.f);
    v1.x = fmaxf(v1.x, 0.f); v1.y = fmaxf(v1.y, 0.f); v1.z = fmaxf(v1.z, 0.f); v1.w = fmaxf(v1.w, 0.f);

    float s = v0.x + v0.y + v0.z + v0.w + v1.x + v1.y + v1.z + v1.w;
#pragma unroll
    for (int o = 16; o > 0; o >>= 1) s += __shfl_xor_sync(0xffffffffu, s, o);
    float mu = s * (1.0f / 256.0f);
    float q = (v0.x - mu) * (v0.x - mu) + (v0.y - mu) * (v0.y - mu)
            + (v0.z - mu) * (v0.z - mu) + (v0.w - mu) * (v0.w - mu)
            + (v1.x - mu) * (v1.x - mu) + (v1.y - mu) * (v1.y - mu)
            + (v1.z - mu) * (v1.z - mu) + (v1.w - mu) * (v1.w - mu);
#pragma unroll
    for (int o = 16; o > 0; o >>= 1) q += __shfl_xor_sync(0xffffffffu, q, o);
    float rs = rsqrtf(q * (1.0f / 256.0f) + 1e-5f);

    const float4* gp = (const float4*)g;
    const float4* bp = (const float4*)b;
    float4 g0 = gp[lane], g1 = gp[32 + lane], b0 = bp[lane], b1 = bp[32 + lane];
    float4 o0, o1;
    o0.x = (v0.x - mu) * rs * g0.x + b0.x; o0.y = (v0.y - mu) * rs * g0.y + b0.y;
    o0.z = (v0.z - mu) * rs * g0.z + b0.z; o0.w = (v0.w - mu) * rs * g0.w + b0.w;
    o1.x = (v1.x - mu) * rs * g1.x + b1.x; o1.y = (v1.y - mu) * rs * g1.y + b1.y;
    o1.z = (v1.z - mu) * rs * g1.z + b1.z; o1.w = (v1.w - mu) * rs * g1.w + b1.w;

    if (!SPLIT) {
        float4* op = (float4*)(out + (size_t)row * 256);
        op[lane] = o0; op[32 + lane] = o1;
    } else {
        __nv_bfloat16* base = split + (size_t)row * 768;
        // o0 -> cols lane*4..+3 ; o1 -> cols 128+lane*4..+3
        float vv[2][4] = {{o0.x, o0.y, o0.z, o0.w}, {o1.x, o1.y, o1.z, o1.w}};
#pragma unroll
        for (int h2 = 0; h2 < 2; ++h2) {
            int c = h2 * 128 + lane * 4;
            __nv_bfloat16 hA = __float2bfloat16(vv[h2][0]);
            __nv_bfloat16 hB = __float2bfloat16(vv[h2][1]);
            __nv_bfloat16 hC = __float2bfloat16(vv[h2][2]);
            __nv_bfloat16 hD = __float2bfloat16(vv[h2][3]);
            __nv_bfloat162 H0(hA, hB), H1(hC, hD);
            __nv_bfloat162 L0(__float2bfloat16(vv[h2][0] - __bfloat162float(hA)),
                              __float2bfloat16(vv[h2][1] - __bfloat162float(hB)));
            __nv_bfloat162 L1(__float2bfloat16(vv[h2][2] - __bfloat162float(hC)),
                              __float2bfloat16(vv[h2][3] - __bfloat162float(hD)));
            ((__nv_bfloat162*)(base + c))[0]       = H0;
            ((__nv_bfloat162*)(base + c))[1]       = H1;
            ((__nv_bfloat162*)(base + 256 + c))[0] = L0;
            ((__nv_bfloat162*)(base + 256 + c))[1] = L1;
            ((__nv_bfloat162*)(base + 512 + c))[0] = H0;
            ((__nv_bfloat162*)(base + 512 + c))[1] = H1;
        }
    }
}

// ---------------------------------------------------------------------------
// Host launcher
// ---------------------------------------------------------------------------
extern "C" void kernel_launch(void* const* d_in, const int* in_sizes, int n_in,
                              void* d_out, int out_size)
{
    const float* x       = (const float*)d_in[0];
    const float* nw      = (const float*)d_in[1];
    const int*   esrc    = (const int*)d_in[2];
    const int*   etgt    = (const int*)d_in[3];
    const float* Wrel0   = (const float*)d_in[4];
    const float* Wself0w = (const float*)d_in[5];
    const float* Wself0b = (const float*)d_in[6];
    const float* ln0g    = (const float*)d_in[7];
    const float* ln0b    = (const float*)d_in[8];
    const float* Wrel1   = (const float*)d_in[9];
    const float* Wself1w = (const float*)d_in[10];
    const float* Wself1b = (const float*)d_in[11];
    const float* ln1g    = (const float*)d_in[12];
    const float* ln1b    = (const float*)d_in[13];
    float* out = (float*)d_out;

    __nv_bfloat16 *a, *bt;
    float *selfb, *y, *agg, *cnt;
    cudaGetSymbolAddress((void**)&a,     g_a);
    cudaGetSymbolAddress((void**)&bt,    g_bt);
    cudaGetSymbolAddress((void**)&selfb, g_self);
    cudaGetSymbolAddress((void**)&y,     g_y);
    cudaGetSymbolAddress((void**)&agg,   g_agg);
    cudaGetSymbolAddress((void**)&cnt,   g_cnt);

    cudaFuncSetAttribute(hmma_gemm_kernel<2304>,
                         cudaFuncAttributeMaxDynamicSharedMemorySize, GEMM_SMEM);
    cudaFuncSetAttribute(hmma_gemm_kernel<768>,
                         cudaFuncAttributeMaxDynamicSharedMemorySize, GEMM_SMEM);

    const int gy = (NN + 127) / 128;          // 391 m-blocks
    const int gnx = NT / 128;                 // 18 n-blocks
    const int scat_blocks = (RR * EE * 32 + 255) / 256;

    // Inverse neighbor counts
    cudaMemsetAsync(cnt, 0, (size_t)RR * NN * sizeof(float));
    count_kernel<<<(RR * EE + 255) / 256, 256>>>(etgt, cnt);
    invert_kernel<<<(RR * NN + 255) / 256, 256>>>(cnt);

    // ---- Layer 0 (K=768, K'=2304) ----
    convert_split3_kernel<768><<<(int)(((size_t)NN * 192 + 255) / 256), 256>>>(x, a, NN);
    wtrans3_kernel<768><<<dim3(768 / 32, NT / 32), 256>>>(Wself0w, Wrel0, bt);
    hmma_gemm_kernel<2304><<<dim3(gnx, gy), 256, GEMM_SMEM>>>(a, bt, selfb, y, NN);
    init_agg_kernel<<<(int)(((size_t)NN * 64 + 255) / 256), 256>>>(selfb, Wself0b, agg);
    scatter256_kernel<<<scat_blocks, 256>>>(y, esrc, etgt, nw, cnt, agg);
    // LN + fused bf16 split of h for layer 1 (writes g_a directly)
    ln_kernel<true><<<(NN + 7) / 8, 256>>>(agg, ln0g, ln0b, nullptr, a);

    // ---- Layer 1 (K=256, K'=768) ----
    wtrans3_kernel<256><<<dim3(256 / 32, NT / 32), 256>>>(Wself1w, Wrel1, bt);
    hmma_gemm_kernel<768><<<dim3(gnx, gy), 256, GEMM_SMEM>>>(a, bt, selfb, y, NN);
    init_agg_kernel<<<(int)(((size_t)NN * 64 + 255) / 256), 256>>>(selfb, Wself1b, agg);
    scatter256_kernel<<<scat_blocks, 256>>>(y, esrc, etgt, nw, cnt, agg);
    ln_kernel<false><<<(NN + 7) / 8, 256>>>(agg, ln1g, ln1b, out, nullptr);
}